// round 2
// baseline (speedup 1.0000x reference)
#include <cuda_runtime.h>
#include <cstdint>

// Problem constants
#define NROWS 65536   // 32 * 2048
#define DIMS  512
#define CODES 1024

// Scratch (device globals — allocation is forbidden)
__device__ float g_enorm[CODES];
__device__ float g_znorm[NROWS];

// ---------------------------------------------------------------------------
// Kernel 0a: ||e_k||^2 (fp64 accumulate -> fp32), one warp per code row
// ---------------------------------------------------------------------------
__global__ void enorm_kernel(const float* __restrict__ emb) {
    int warp = (blockIdx.x * blockDim.x + threadIdx.x) >> 5;
    int lane = threadIdx.x & 31;
    if (warp >= CODES) return;
    const float4* row = reinterpret_cast<const float4*>(emb + (size_t)warp * DIMS);
    double s = 0.0;
#pragma unroll
    for (int i = 0; i < 4; i++) {
        float4 v = row[lane + i * 32];
        s += (double)v.x * v.x + (double)v.y * v.y
           + (double)v.z * v.z + (double)v.w * v.w;
    }
#pragma unroll
    for (int off = 16; off > 0; off >>= 1)
        s += __shfl_xor_sync(0xffffffffu, s, off);
    if (lane == 0) g_enorm[warp] = (float)s;
}

// ---------------------------------------------------------------------------
// Kernel 0b: ||z_r||^2 (fp64 accumulate -> fp32), one warp per row
// ---------------------------------------------------------------------------
__global__ void znorm_kernel(const float* __restrict__ z) {
    int warp = (blockIdx.x * blockDim.x + threadIdx.x) >> 5;
    int lane = threadIdx.x & 31;
    if (warp >= NROWS) return;
    const float4* row = reinterpret_cast<const float4*>(z + (size_t)warp * DIMS);
    double s = 0.0;
#pragma unroll
    for (int i = 0; i < 4; i++) {
        float4 v = row[lane + i * 32];
        s += (double)v.x * v.x + (double)v.y * v.y
           + (double)v.z * v.z + (double)v.w * v.w;
    }
#pragma unroll
    for (int off = 16; off > 0; off >>= 1)
        s += __shfl_xor_sync(0xffffffffu, s, off);
    if (lane == 0) g_znorm[warp] = (float)s;
}

// ---------------------------------------------------------------------------
// Kernel 1: fused distance-GEMM + argmin + gather
//   score emulates the reference's fp32 rounding pipeline:
//     s = fl32( fl32(zn_r + en_c) - fl32(2 * dot(z_r, e_c)) )
//   Ties (equal fp32 s) resolve to the LOWEST code index, matching jnp.argmin.
// ---------------------------------------------------------------------------
__global__ __launch_bounds__(256, 2)
void vq_argmin_kernel(const float* __restrict__ z,
                      const float* __restrict__ emb,
                      float* __restrict__ out) {
    __shared__ __align__(16) float smem[2 * 16 * 128];   // 16 KB, repurposed
    float* Zs = smem;              // [k][row]
    float* Es = smem + 16 * 128;   // [k][code]
    __shared__ int srow[128];

    const int t    = threadIdx.x;
    const int row0 = blockIdx.x * 128;
    const int tx = t & 15;         // code group  (8 codes)
    const int ty = t >> 4;         // row group   (8 rows)

    const int lr = t >> 2;         // 0..63 (load row)
    const int dq = t & 3;          // dim quad

    // per-thread row norms (row0 + ty*8 + i)
    float zn[8];
#pragma unroll
    for (int i = 0; i < 8; i++) zn[i] = g_znorm[row0 + ty * 8 + i];

    float best[8];
    int   bidx[8];
#pragma unroll
    for (int i = 0; i < 8; i++) { best[i] = 3.4e38f; bidx[i] = 0; }

    for (int n0 = 0; n0 < CODES; n0 += 128) {
        float acc[8][8];
#pragma unroll
        for (int i = 0; i < 8; i++)
#pragma unroll
            for (int j = 0; j < 8; j++) acc[i][j] = 0.f;

        for (int dk = 0; dk < DIMS; dk += 16) {
            float4 za = *reinterpret_cast<const float4*>(
                z + (size_t)(row0 + lr) * DIMS + dk + dq * 4);
            float4 zb = *reinterpret_cast<const float4*>(
                z + (size_t)(row0 + lr + 64) * DIMS + dk + dq * 4);
            float4 ea = *reinterpret_cast<const float4*>(
                emb + (size_t)(n0 + lr) * DIMS + dk + dq * 4);
            float4 eb = *reinterpret_cast<const float4*>(
                emb + (size_t)(n0 + lr + 64) * DIMS + dk + dq * 4);

            __syncthreads();
            Zs[(dq * 4 + 0) * 128 + lr] = za.x;
            Zs[(dq * 4 + 1) * 128 + lr] = za.y;
            Zs[(dq * 4 + 2) * 128 + lr] = za.z;
            Zs[(dq * 4 + 3) * 128 + lr] = za.w;
            Zs[(dq * 4 + 0) * 128 + lr + 64] = zb.x;
            Zs[(dq * 4 + 1) * 128 + lr + 64] = zb.y;
            Zs[(dq * 4 + 2) * 128 + lr + 64] = zb.z;
            Zs[(dq * 4 + 3) * 128 + lr + 64] = zb.w;
            Es[(dq * 4 + 0) * 128 + lr] = ea.x;
            Es[(dq * 4 + 1) * 128 + lr] = ea.y;
            Es[(dq * 4 + 2) * 128 + lr] = ea.z;
            Es[(dq * 4 + 3) * 128 + lr] = ea.w;
            Es[(dq * 4 + 0) * 128 + lr + 64] = eb.x;
            Es[(dq * 4 + 1) * 128 + lr + 64] = eb.y;
            Es[(dq * 4 + 2) * 128 + lr + 64] = eb.z;
            Es[(dq * 4 + 3) * 128 + lr + 64] = eb.w;
            __syncthreads();

#pragma unroll
            for (int k = 0; k < 16; k++) {
                float zf[8], ef[8];
                *reinterpret_cast<float4*>(zf)     = *reinterpret_cast<float4*>(&Zs[k * 128 + ty * 8]);
                *reinterpret_cast<float4*>(zf + 4) = *reinterpret_cast<float4*>(&Zs[k * 128 + ty * 8 + 4]);
                *reinterpret_cast<float4*>(ef)     = *reinterpret_cast<float4*>(&Es[k * 128 + tx * 8]);
                *reinterpret_cast<float4*>(ef + 4) = *reinterpret_cast<float4*>(&Es[k * 128 + tx * 8 + 4]);
#pragma unroll
                for (int i = 0; i < 8; i++)
#pragma unroll
                    for (int j = 0; j < 8; j++)
                        acc[i][j] = fmaf(zf[i], ef[j], acc[i][j]);
            }
        }

        // ---- epilogue: reference-rounding score + running argmin ----
        float en[8];
        *reinterpret_cast<float4*>(en)     = *reinterpret_cast<const float4*>(&g_enorm[n0 + tx * 8]);
        *reinterpret_cast<float4*>(en + 4) = *reinterpret_cast<const float4*>(&g_enorm[n0 + tx * 8 + 4]);
#pragma unroll
        for (int i = 0; i < 8; i++) {
#pragma unroll
            for (int j = 0; j < 8; j++) {
                // emulate ((zn + en) - 2*mm) with explicit fp32 rounding, no FMA
                float tsum = __fadd_rn(zn[i], en[j]);
                float s    = __fsub_rn(tsum, __fmul_rn(2.0f, acc[i][j]));
                int   c    = n0 + tx * 8 + j;
                if (s < best[i]) { best[i] = s; bidx[i] = c; }  // strict <: first index wins
            }
        }
    }

    // ---- cross-thread argmin per row (tie -> lowest index) ----
    __syncthreads();
    float* sbest = smem;                           // [row][16]
    int*   sidx  = reinterpret_cast<int*>(smem + 128 * 16);
#pragma unroll
    for (int i = 0; i < 8; i++) {
        sbest[(ty * 8 + i) * 16 + tx] = best[i];
        sidx [(ty * 8 + i) * 16 + tx] = bidx[i];
    }
    __syncthreads();
    if (t < 128) {
        float b  = sbest[t * 16];
        int   bi = sidx [t * 16];
#pragma unroll
        for (int x = 1; x < 16; x++) {
            float v  = sbest[t * 16 + x];
            int   vi = sidx [t * 16 + x];
            if (v < b || (v == b && vi < bi)) { b = v; bi = vi; }
        }
        srow[t] = bi;
    }
    __syncthreads();

    // ---- gather: out[row] = emb[idx] ----
    float4*       out4 = reinterpret_cast<float4*>(out + (size_t)row0 * DIMS);
    const float4* emb4 = reinterpret_cast<const float4*>(emb);
    for (int v = t; v < 128 * (DIMS / 4); v += 256) {
        int r  = v >> 7;
        int c4 = v & 127;
        out4[(size_t)r * 128 + c4] = emb4[(size_t)srow[r] * 128 + c4];
    }
}

// ---------------------------------------------------------------------------
// Launch
// ---------------------------------------------------------------------------
extern "C" void kernel_launch(void* const* d_in, const int* in_sizes, int n_in,
                              void* d_out, int out_size) {
    const float* z   = (const float*)d_in[0];   // [32,2048,512] fp32
    const float* emb = (const float*)d_in[1];   // [1024,512] fp32
    float* out = (float*)d_out;

    enorm_kernel<<<(CODES * 32 + 255) / 256, 256>>>(emb);
    znorm_kernel<<<(NROWS * 32 + 255) / 256, 256>>>(z);
    vq_argmin_kernel<<<NROWS / 128, 256>>>(z, emb, out);
}

// round 3
// speedup vs baseline: 1.0094x; 1.0094x over previous
#include <cuda_runtime.h>
#include <cstdint>

// Problem constants
#define NROWS 65536   // 32 * 2048
#define DIMS  512
#define CODES 1024

// Scratch (device globals — allocation is forbidden)
__device__ float g_enorm[CODES];
__device__ float g_znorm[NROWS];

// ---------------------------------------------------------------------------
// Kernel 0a: ||e_k||^2 (fp64 accumulate -> fp32), one warp per code row
// ---------------------------------------------------------------------------
__global__ void enorm_kernel(const float* __restrict__ emb) {
    int warp = (blockIdx.x * blockDim.x + threadIdx.x) >> 5;
    int lane = threadIdx.x & 31;
    if (warp >= CODES) return;
    const float4* row = reinterpret_cast<const float4*>(emb + (size_t)warp * DIMS);
    double s = 0.0;
#pragma unroll
    for (int i = 0; i < 4; i++) {
        float4 v = row[lane + i * 32];
        s += (double)v.x * v.x + (double)v.y * v.y
           + (double)v.z * v.z + (double)v.w * v.w;
    }
#pragma unroll
    for (int off = 16; off > 0; off >>= 1)
        s += __shfl_xor_sync(0xffffffffu, s, off);
    if (lane == 0) g_enorm[warp] = (float)s;
}

// ---------------------------------------------------------------------------
// Kernel 0b: ||z_r||^2 (fp64 accumulate -> fp32), one warp per row
// ---------------------------------------------------------------------------
__global__ void znorm_kernel(const float* __restrict__ z) {
    int warp = (blockIdx.x * blockDim.x + threadIdx.x) >> 5;
    int lane = threadIdx.x & 31;
    if (warp >= NROWS) return;
    const float4* row = reinterpret_cast<const float4*>(z + (size_t)warp * DIMS);
    double s = 0.0;
#pragma unroll
    for (int i = 0; i < 4; i++) {
        float4 v = row[lane + i * 32];
        s += (double)v.x * v.x + (double)v.y * v.y
           + (double)v.z * v.z + (double)v.w * v.w;
    }
#pragma unroll
    for (int off = 16; off > 0; off >>= 1)
        s += __shfl_xor_sync(0xffffffffu, s, off);
    if (lane == 0) g_znorm[warp] = (float)s;
}

// ---------------------------------------------------------------------------
// Kernel 1: fused distance-GEMM (packed f32x2 FMA) + argmin + gather
//   score = fl32( fl32(zn_r + en_c) - fl32(2 * dot(z_r, e_c)) )  [ref rounding]
//   Ties resolve to the LOWEST code index (jnp.argmin semantics).
//   f32x2 lanes are IEEE-rn fp32 -> bitwise identical to the scalar version.
// ---------------------------------------------------------------------------
__global__ __launch_bounds__(256, 2)
void vq_argmin_kernel(const float* __restrict__ z,
                      const float* __restrict__ emb,
                      float* __restrict__ out) {
    __shared__ __align__(16) float smem[2 * 16 * 128];   // 16 KB, repurposed
    float* Zs = smem;              // [k][row]
    float* Es = smem + 16 * 128;   // [k][code]
    __shared__ int srow[128];

    const int t    = threadIdx.x;
    const int row0 = blockIdx.x * 128;
    const int tx = t & 15;         // code group  (8 codes)
    const int ty = t >> 4;         // row group   (8 rows)

    const int lr = t >> 2;         // 0..63 (load row)
    const int dq = t & 3;          // dim quad

    float zn[8];
#pragma unroll
    for (int i = 0; i < 8; i++) zn[i] = g_znorm[row0 + ty * 8 + i];

    float best[8];
    int   bidx[8];
#pragma unroll
    for (int i = 0; i < 8; i++) { best[i] = 3.4e38f; bidx[i] = 0; }

    const float* zp0 = z   + (size_t)(row0 + lr) * DIMS + dq * 4;
    const float* zp1 = z   + (size_t)(row0 + lr + 64) * DIMS + dq * 4;

    for (int n0 = 0; n0 < CODES; n0 += 128) {
        // packed accumulators: acc[i][j2] = {acc(i,2*j2), acc(i,2*j2+1)}
        unsigned long long acc[8][4];
#pragma unroll
        for (int i = 0; i < 8; i++)
#pragma unroll
            for (int j = 0; j < 4; j++) acc[i][j] = 0ULL;

        const float* ep0 = emb + (size_t)(n0 + lr) * DIMS + dq * 4;
        const float* ep1 = emb + (size_t)(n0 + lr + 64) * DIMS + dq * 4;

        // prefetch first tile
        float4 za = *reinterpret_cast<const float4*>(zp0);
        float4 zb = *reinterpret_cast<const float4*>(zp1);
        float4 ea = *reinterpret_cast<const float4*>(ep0);
        float4 eb = *reinterpret_cast<const float4*>(ep1);

        for (int dk = 0; dk < DIMS; dk += 16) {
            __syncthreads();   // previous k-chunk fully consumed
            Zs[(dq * 4 + 0) * 128 + lr] = za.x;
            Zs[(dq * 4 + 1) * 128 + lr] = za.y;
            Zs[(dq * 4 + 2) * 128 + lr] = za.z;
            Zs[(dq * 4 + 3) * 128 + lr] = za.w;
            Zs[(dq * 4 + 0) * 128 + lr + 64] = zb.x;
            Zs[(dq * 4 + 1) * 128 + lr + 64] = zb.y;
            Zs[(dq * 4 + 2) * 128 + lr + 64] = zb.z;
            Zs[(dq * 4 + 3) * 128 + lr + 64] = zb.w;
            Es[(dq * 4 + 0) * 128 + lr] = ea.x;
            Es[(dq * 4 + 1) * 128 + lr] = ea.y;
            Es[(dq * 4 + 2) * 128 + lr] = ea.z;
            Es[(dq * 4 + 3) * 128 + lr] = ea.w;
            Es[(dq * 4 + 0) * 128 + lr + 64] = eb.x;
            Es[(dq * 4 + 1) * 128 + lr + 64] = eb.y;
            Es[(dq * 4 + 2) * 128 + lr + 64] = eb.z;
            Es[(dq * 4 + 3) * 128 + lr + 64] = eb.w;
            __syncthreads();

            // prefetch next tile (latency hides under the 16 k-steps below)
            if (dk + 16 < DIMS) {
                za = *reinterpret_cast<const float4*>(zp0 + dk + 16);
                zb = *reinterpret_cast<const float4*>(zp1 + dk + 16);
                ea = *reinterpret_cast<const float4*>(ep0 + dk + 16);
                eb = *reinterpret_cast<const float4*>(ep1 + dk + 16);
            }

#pragma unroll
            for (int k = 0; k < 16; k++) {
                float zf[8];
                *reinterpret_cast<float4*>(zf)     = *reinterpret_cast<float4*>(&Zs[k * 128 + ty * 8]);
                *reinterpret_cast<float4*>(zf + 4) = *reinterpret_cast<float4*>(&Zs[k * 128 + ty * 8 + 4]);
                unsigned long long ep[4];
                {
                    ulonglong2 e0 = *reinterpret_cast<ulonglong2*>(&Es[k * 128 + tx * 8]);
                    ulonglong2 e1 = *reinterpret_cast<ulonglong2*>(&Es[k * 128 + tx * 8 + 4]);
                    ep[0] = e0.x; ep[1] = e0.y; ep[2] = e1.x; ep[3] = e1.y;
                }
                unsigned long long zp[8];
#pragma unroll
                for (int i = 0; i < 8; i++)
                    asm("mov.b64 %0, {%1, %1};" : "=l"(zp[i]) : "f"(zf[i]));
#pragma unroll
                for (int i = 0; i < 8; i++)
#pragma unroll
                    for (int j = 0; j < 4; j++)
                        asm("fma.rn.f32x2 %0, %1, %2, %0;"
                            : "+l"(acc[i][j]) : "l"(zp[i]), "l"(ep[j]));
            }
        }

        // ---- epilogue: reference-rounding score + running argmin ----
        float en[8];
        *reinterpret_cast<float4*>(en)     = *reinterpret_cast<const float4*>(&g_enorm[n0 + tx * 8]);
        *reinterpret_cast<float4*>(en + 4) = *reinterpret_cast<const float4*>(&g_enorm[n0 + tx * 8 + 4]);
#pragma unroll
        for (int i = 0; i < 8; i++) {
#pragma unroll
            for (int j = 0; j < 8; j++) {
                unsigned long long p = acc[i][j >> 1];
                unsigned int bits = (j & 1) ? (unsigned int)(p >> 32)
                                            : (unsigned int)(p & 0xffffffffu);
                float d = __uint_as_float(bits);
                float tsum = __fadd_rn(zn[i], en[j]);
                float s    = __fsub_rn(tsum, __fmul_rn(2.0f, d));
                int   c    = n0 + tx * 8 + j;
                if (s < best[i]) { best[i] = s; bidx[i] = c; }  // strict <: first index wins
            }
        }
    }

    // ---- cross-thread argmin per row (tie -> lowest index) ----
    __syncthreads();
    float* sbest = smem;                           // [row][16]
    int*   sidx  = reinterpret_cast<int*>(smem + 128 * 16);
#pragma unroll
    for (int i = 0; i < 8; i++) {
        sbest[(ty * 8 + i) * 16 + tx] = best[i];
        sidx [(ty * 8 + i) * 16 + tx] = bidx[i];
    }
    __syncthreads();
    if (t < 128) {
        float b  = sbest[t * 16];
        int   bi = sidx [t * 16];
#pragma unroll
        for (int x = 1; x < 16; x++) {
            float v  = sbest[t * 16 + x];
            int   vi = sidx [t * 16 + x];
            if (v < b || (v == b && vi < bi)) { b = v; bi = vi; }
        }
        srow[t] = bi;
    }
    __syncthreads();

    // ---- gather: out[row] = emb[idx] ----
    float4*       out4 = reinterpret_cast<float4*>(out + (size_t)row0 * DIMS);
    const float4* emb4 = reinterpret_cast<const float4*>(emb);
    for (int v = t; v < 128 * (DIMS / 4); v += 256) {
        int r  = v >> 7;
        int c4 = v & 127;
        out4[(size_t)r * 128 + c4] = emb4[(size_t)srow[r] * 128 + c4];
    }
}

// ---------------------------------------------------------------------------
// Launch
// ---------------------------------------------------------------------------
extern "C" void kernel_launch(void* const* d_in, const int* in_sizes, int n_in,
                              void* d_out, int out_size) {
    const float* z   = (const float*)d_in[0];   // [32,2048,512] fp32
    const float* emb = (const float*)d_in[1];   // [1024,512] fp32
    float* out = (float*)d_out;

    enorm_kernel<<<(CODES * 32 + 255) / 256, 256>>>(emb);
    znorm_kernel<<<(NROWS * 32 + 255) / 256, 256>>>(z);
    vq_argmin_kernel<<<NROWS / 128, 256>>>(z, emb, out);
}

// round 6
// speedup vs baseline: 1.1953x; 1.1841x over previous
#include <cuda_runtime.h>
#include <cstdint>

// Problem constants
#define NROWS 65536   // 32 * 2048
#define DIMS  512
#define CODES 1024

#define MT  128       // rows per CTA (TC kernel)
#define NT2 128       // codes per tile
#define KC  16        // K floats per staged chunk
#define NCH (DIMS / KC)      // 32 chunks
#define NTL (CODES / NT2)    // 8 tiles

#define MARGIN 2.5e-4f       // > 3 grid-ulps at the ~512 score binade

// Scratch (device globals — allocation is forbidden)
__device__ float g_enorm[CODES];
__device__ float g_znorm[NROWS];
__device__ int   g_flagcnt;
__device__ int   g_flagrows[NROWS];
__device__ unsigned long long g_best[NROWS];

// ---------------------------------------------------------------------------
// Helpers
// ---------------------------------------------------------------------------
__device__ __forceinline__ float tf32r(float x) {
    uint32_t r;
    asm("cvt.rna.tf32.f32 %0, %1;" : "=r"(r) : "f"(x));
    return __uint_as_float(r);
}

__device__ __forceinline__ void mma_tf32(float* c,
                                         uint32_t a0, uint32_t a1, uint32_t a2, uint32_t a3,
                                         uint32_t b0, uint32_t b1) {
    asm volatile(
        "mma.sync.aligned.m16n8k8.row.col.f32.tf32.tf32.f32 "
        "{%0,%1,%2,%3}, {%4,%5,%6,%7}, {%8,%9}, {%0,%1,%2,%3};"
        : "+f"(c[0]), "+f"(c[1]), "+f"(c[2]), "+f"(c[3])
        : "r"(a0), "r"(a1), "r"(a2), "r"(a3), "r"(b0), "r"(b1));
}

// swizzled smem index for a [128][16] float tile
__device__ __forceinline__ int lds_idx(int r, int k) {
    return (r << 4) + ((((k >> 2) ^ ((r >> 1) & 3)) & 3) << 2) + (k & 3);
}

// ---------------------------------------------------------------------------
// Norm kernels (fp64 accumulate -> fp32), one warp per row
// ---------------------------------------------------------------------------
__global__ void enorm_kernel(const float* __restrict__ emb) {
    if (blockIdx.x == 0 && threadIdx.x == 0) g_flagcnt = 0;  // reset per replay
    int warp = (blockIdx.x * blockDim.x + threadIdx.x) >> 5;
    int lane = threadIdx.x & 31;
    if (warp >= CODES) return;
    const float4* row = reinterpret_cast<const float4*>(emb + (size_t)warp * DIMS);
    double s = 0.0;
#pragma unroll
    for (int i = 0; i < 4; i++) {
        float4 v = row[lane + i * 32];
        s += (double)v.x * v.x + (double)v.y * v.y
           + (double)v.z * v.z + (double)v.w * v.w;
    }
#pragma unroll
    for (int off = 16; off > 0; off >>= 1)
        s += __shfl_xor_sync(0xffffffffu, s, off);
    if (lane == 0) g_enorm[warp] = (float)s;
}

__global__ void znorm_kernel(const float* __restrict__ z) {
    int warp = (blockIdx.x * blockDim.x + threadIdx.x) >> 5;
    int lane = threadIdx.x & 31;
    if (warp >= NROWS) return;
    const float4* row = reinterpret_cast<const float4*>(z + (size_t)warp * DIMS);
    double s = 0.0;
#pragma unroll
    for (int i = 0; i < 4; i++) {
        float4 v = row[lane + i * 32];
        s += (double)v.x * v.x + (double)v.y * v.y
           + (double)v.z * v.z + (double)v.w * v.w;
    }
#pragma unroll
    for (int off = 16; off > 0; off >>= 1)
        s += __shfl_xor_sync(0xffffffffu, s, off);
    if (lane == 0) g_znorm[warp] = (float)s;
}

// ---------------------------------------------------------------------------
// TC kernel: 3xTF32 mma.sync GEMM + top-2 argmin + flag + gather
// ---------------------------------------------------------------------------
__global__ __launch_bounds__(256, 2)
void vq_mma_kernel(const float* __restrict__ z,
                   const float* __restrict__ emb,
                   float* __restrict__ out) {
    __shared__ __align__(16) float sAh[128 * KC];
    __shared__ __align__(16) float sAl[128 * KC];
    __shared__ __align__(16) float sBh[128 * KC];
    __shared__ __align__(16) float sBl[128 * KC];
    __shared__ float sbest[128 * 4];
    __shared__ float sb2  [128 * 4];
    __shared__ int   sidn [128 * 4];
    __shared__ int   srow [128];

    const int t    = threadIdx.x;
    const int lane = t & 31;
    const int wid  = t >> 5;
    const int row0 = blockIdx.x * MT;
    const int wm = (wid & 1) * 64;
    const int wn = (wid >> 1) * 32;
    const int lr4 = lane >> 2;
    const int lc  = lane & 3;

    float zn[8];
#pragma unroll
    for (int mi = 0; mi < 4; mi++)
#pragma unroll
        for (int h = 0; h < 2; h++)
            zn[mi * 2 + h] = g_znorm[row0 + wm + mi * 16 + lr4 + h * 8];

    float best[8], b2[8];
    int   bidx[8];
#pragma unroll
    for (int i = 0; i < 8; i++) { best[i] = 3.4e38f; b2[i] = 3.4e38f; bidx[i] = 0; }

    for (int nt = 0; nt < NTL; nt++) {
        const int n0 = nt * NT2;

        float acc[4][4][4];
#pragma unroll
        for (int mi = 0; mi < 4; mi++)
#pragma unroll
            for (int nj = 0; nj < 4; nj++)
#pragma unroll
                for (int q = 0; q < 4; q++) acc[mi][nj][q] = 0.f;

        float4 pa[2], pb[2];
#pragma unroll
        for (int i = 0; i < 2; i++) {
            int v = t + 256 * i;
            int r = v >> 2, q = v & 3;
            pa[i] = *reinterpret_cast<const float4*>(z   + (size_t)(row0 + r) * DIMS + q * 4);
            pb[i] = *reinterpret_cast<const float4*>(emb + (size_t)(n0  + r) * DIMS + q * 4);
        }

        for (int c = 0; c < NCH; c++) {
            __syncthreads();
#pragma unroll
            for (int i = 0; i < 2; i++) {
                int v = t + 256 * i;
                int r = v >> 2, q = v & 3;
                int off = (r << 4) + (((q ^ ((r >> 1) & 3)) & 3) << 2);

                float4 x = pa[i];
                float4 hi, lo;
                hi.x = tf32r(x.x); lo.x = tf32r(__fsub_rn(x.x, hi.x));
                hi.y = tf32r(x.y); lo.y = tf32r(__fsub_rn(x.y, hi.y));
                hi.z = tf32r(x.z); lo.z = tf32r(__fsub_rn(x.z, hi.z));
                hi.w = tf32r(x.w); lo.w = tf32r(__fsub_rn(x.w, hi.w));
                *reinterpret_cast<float4*>(&sAh[off]) = hi;
                *reinterpret_cast<float4*>(&sAl[off]) = lo;

                x = pb[i];
                hi.x = tf32r(x.x); lo.x = tf32r(__fsub_rn(x.x, hi.x));
                hi.y = tf32r(x.y); lo.y = tf32r(__fsub_rn(x.y, hi.y));
                hi.z = tf32r(x.z); lo.z = tf32r(__fsub_rn(x.z, hi.z));
                hi.w = tf32r(x.w); lo.w = tf32r(__fsub_rn(x.w, hi.w));
                *reinterpret_cast<float4*>(&sBh[off]) = hi;
                *reinterpret_cast<float4*>(&sBl[off]) = lo;
            }
            __syncthreads();

            if (c + 1 < NCH) {
                const int k0n = (c + 1) * KC;
#pragma unroll
                for (int i = 0; i < 2; i++) {
                    int v = t + 256 * i;
                    int r = v >> 2, q = v & 3;
                    pa[i] = *reinterpret_cast<const float4*>(
                        z   + (size_t)(row0 + r) * DIMS + k0n + q * 4);
                    pb[i] = *reinterpret_cast<const float4*>(
                        emb + (size_t)(n0  + r) * DIMS + k0n + q * 4);
                }
            }

#pragma unroll
            for (int ks = 0; ks < 2; ks++) {
                uint32_t Bh[4][2], Bl[4][2];
#pragma unroll
                for (int nj = 0; nj < 4; nj++) {
                    int n = wn + nj * 8 + lr4;
                    int k = ks * 8 + lc;
                    int i0 = lds_idx(n, k);
                    int i1 = lds_idx(n, k + 4);
                    Bh[nj][0] = __float_as_uint(sBh[i0]);
                    Bh[nj][1] = __float_as_uint(sBh[i1]);
                    Bl[nj][0] = __float_as_uint(sBl[i0]);
                    Bl[nj][1] = __float_as_uint(sBl[i1]);
                }
#pragma unroll
                for (int mi = 0; mi < 4; mi++) {
                    int r = wm + mi * 16 + lr4;
                    int k = ks * 8 + lc;
                    int i00 = lds_idx(r,     k);
                    int i10 = lds_idx(r + 8, k);
                    int i01 = lds_idx(r,     k + 4);
                    int i11 = lds_idx(r + 8, k + 4);
                    uint32_t Ah0 = __float_as_uint(sAh[i00]);
                    uint32_t Ah1 = __float_as_uint(sAh[i10]);
                    uint32_t Ah2 = __float_as_uint(sAh[i01]);
                    uint32_t Ah3 = __float_as_uint(sAh[i11]);
                    uint32_t Al0 = __float_as_uint(sAl[i00]);
                    uint32_t Al1 = __float_as_uint(sAl[i10]);
                    uint32_t Al2 = __float_as_uint(sAl[i01]);
                    uint32_t Al3 = __float_as_uint(sAl[i11]);
#pragma unroll
                    for (int nj = 0; nj < 4; nj++) {
                        mma_tf32(acc[mi][nj], Ah0, Ah1, Ah2, Ah3, Bh[nj][0], Bh[nj][1]);
                        mma_tf32(acc[mi][nj], Ah0, Ah1, Ah2, Ah3, Bl[nj][0], Bl[nj][1]);
                        mma_tf32(acc[mi][nj], Al0, Al1, Al2, Al3, Bh[nj][0], Bh[nj][1]);
                    }
                }
            }
        }

        // ---- epilogue: ref-rounding score + running top-2 ----
#pragma unroll
        for (int mi = 0; mi < 4; mi++) {
#pragma unroll
            for (int nj = 0; nj < 4; nj++) {
                int cbase = n0 + wn + nj * 8 + 2 * lc;
                float en0 = __ldg(&g_enorm[cbase]);
                float en1 = __ldg(&g_enorm[cbase + 1]);
                const float* cc = acc[mi][nj];
#pragma unroll
                for (int h = 0; h < 2; h++) {
                    int s0i = mi * 2 + h;
                    float s0 = __fsub_rn(__fadd_rn(zn[s0i], en0), __fmul_rn(2.0f, cc[h * 2]));
                    float s1 = __fsub_rn(__fadd_rn(zn[s0i], en1), __fmul_rn(2.0f, cc[h * 2 + 1]));
                    if (s0 < best[s0i]) { b2[s0i] = best[s0i]; best[s0i] = s0; bidx[s0i] = cbase; }
                    else if (s0 < b2[s0i]) b2[s0i] = s0;
                    if (s1 < best[s0i]) { b2[s0i] = best[s0i]; best[s0i] = s1; bidx[s0i] = cbase + 1; }
                    else if (s1 < b2[s0i]) b2[s0i] = s1;
                }
            }
        }
    }

    // ---- cross-lane top-2 merge (lanes sharing a row: lc group) ----
#pragma unroll
    for (int s = 0; s < 8; s++) {
#pragma unroll
        for (int off = 1; off <= 2; off <<= 1) {
            float vb  = __shfl_xor_sync(0xffffffffu, best[s], off);
            float vb2 = __shfl_xor_sync(0xffffffffu, b2[s],   off);
            int   vi  = __shfl_xor_sync(0xffffffffu, bidx[s], off);
            if (vb < best[s]) { b2[s] = fminf(best[s], vb2); best[s] = vb; bidx[s] = vi; }
            else if (vb > best[s]) { b2[s] = fminf(b2[s], vb); }
            else { bidx[s] = min(bidx[s], vi); b2[s] = vb; }
        }
    }
    __syncthreads();
    if (lc == 0) {
#pragma unroll
        for (int mi = 0; mi < 4; mi++)
#pragma unroll
            for (int h = 0; h < 2; h++) {
                int r = wm + mi * 16 + lr4 + h * 8;
                sbest[r * 4 + (wid >> 1)] = best[mi * 2 + h];
                sb2  [r * 4 + (wid >> 1)] = b2  [mi * 2 + h];
                sidn [r * 4 + (wid >> 1)] = bidx[mi * 2 + h];
            }
    }
    __syncthreads();

    if (t < 128) {
        float b  = sbest[t * 4];
        float bb = sb2  [t * 4];
        int   bi = sidn [t * 4];
#pragma unroll
        for (int x = 1; x < 4; x++) {
            float v  = sbest[t * 4 + x];
            float v2 = sb2  [t * 4 + x];
            int   vi = sidn [t * 4 + x];
            if (v < b) { bb = fminf(b, v2); b = v; bi = vi; }
            else if (v > b) { bb = fminf(bb, v); }
            else { bi = min(bi, vi); bb = v; }
        }
        srow[t] = bi;
        if (__fsub_rn(bb, b) < MARGIN) {   // ambiguous -> exact recompute
            int row = row0 + t;
            g_best[row] = ~0ULL;
            int p = atomicAdd(&g_flagcnt, 1);
            g_flagrows[p] = row;
        }
    }
    __syncthreads();

    // ---- gather: out[row] = emb[idx] (flagged rows fixed later) ----
    float4*       out4 = reinterpret_cast<float4*>(out + (size_t)row0 * DIMS);
    const float4* emb4 = reinterpret_cast<const float4*>(emb);
    for (int v = t; v < 128 * (DIMS / 4); v += 256) {
        int r  = v >> 7;
        int c4 = v & 127;
        out4[(size_t)r * 128 + c4] = emb4[(size_t)srow[r] * 128 + c4];
    }
}

// ---------------------------------------------------------------------------
// Exact fallback: R2-identical arithmetic for flagged rows.
//   One block = 64 flagged rows x 128-code group; dot = ascending-k fmaf
//   chain in 16-chunks (bit-identical to the R2 kernel that scored 0.0).
//   Per-row merge across code groups via packed atomicMin (tie -> lowest idx).
// ---------------------------------------------------------------------------
__global__ __launch_bounds__(256)
void vq_exact_kernel(const float* __restrict__ z,
                     const float* __restrict__ emb) {
    __shared__ float Zs[16 * 64];
    __shared__ float Es[16 * 128];
    __shared__ int   rlist[64];

    const int t  = threadIdx.x;
    const int tx = t & 15;    // 8 codes each
    const int ty = t >> 4;    // 4 rows each

    int cnt = g_flagcnt;
    if (cnt <= 0) return;
    int tb = (cnt + 63) >> 6;
    int total = tb * 8;

    for (int task = blockIdx.x; task < total; task += gridDim.x) {
        int rb = task >> 3;
        int cg = task & 7;
        int c0 = cg * 128;

        __syncthreads();
        if (t < 64) {
            int j = rb * 64 + t;
            rlist[t] = g_flagrows[j < cnt ? j : cnt - 1];
        }
        __syncthreads();

        float zn[4];
        int rows[4];
#pragma unroll
        for (int i = 0; i < 4; i++) {
            rows[i] = rlist[ty * 4 + i];
            zn[i] = g_znorm[rows[i]];
        }
        float en[8];
#pragma unroll
        for (int j = 0; j < 8; j++) en[j] = g_enorm[c0 + tx * 8 + j];

        float acc[4][8];
#pragma unroll
        for (int i = 0; i < 4; i++)
#pragma unroll
            for (int j = 0; j < 8; j++) acc[i][j] = 0.f;

        for (int c = 0; c < NCH; c++) {
            const int k0 = c * KC;
            __syncthreads();
            {   // stage Z: 64 rows x 16 K, [k][row]
                int r = t >> 2, q = t & 3;
                float4 x = *reinterpret_cast<const float4*>(
                    z + (size_t)rlist[r] * DIMS + k0 + q * 4);
                Zs[(q * 4 + 0) * 64 + r] = x.x;
                Zs[(q * 4 + 1) * 64 + r] = x.y;
                Zs[(q * 4 + 2) * 64 + r] = x.z;
                Zs[(q * 4 + 3) * 64 + r] = x.w;
            }
#pragma unroll
            for (int i = 0; i < 2; i++) {   // stage E: 128 codes x 16 K
                int v = t + 256 * i;
                int r = v >> 2, q = v & 3;
                float4 x = *reinterpret_cast<const float4*>(
                    emb + (size_t)(c0 + r) * DIMS + k0 + q * 4);
                Es[(q * 4 + 0) * 128 + r] = x.x;
                Es[(q * 4 + 1) * 128 + r] = x.y;
                Es[(q * 4 + 2) * 128 + r] = x.z;
                Es[(q * 4 + 3) * 128 + r] = x.w;
            }
            __syncthreads();

#pragma unroll
            for (int k = 0; k < 16; k++) {
                float zf[4], ef[8];
#pragma unroll
                for (int i = 0; i < 4; i++) zf[i] = Zs[k * 64 + ty * 4 + i];
#pragma unroll
                for (int j = 0; j < 8; j++) ef[j] = Es[k * 128 + tx * 8 + j];
#pragma unroll
                for (int i = 0; i < 4; i++)
#pragma unroll
                    for (int j = 0; j < 8; j++)
                        acc[i][j] = fmaf(zf[i], ef[j], acc[i][j]);
            }
        }

        // score + per-thread argmin (codes ascending -> strict < keeps lowest)
#pragma unroll
        for (int i = 0; i < 4; i++) {
            float bb = 3.4e38f;
            int   bi = 0;
#pragma unroll
            for (int j = 0; j < 8; j++) {
                float s = __fsub_rn(__fadd_rn(zn[i], en[j]),
                                    __fmul_rn(2.0f, acc[i][j]));
                if (s < bb) { bb = s; bi = c0 + tx * 8 + j; }
            }
            unsigned long long pk =
                ((unsigned long long)__float_as_uint(bb) << 32) | (unsigned)bi;
#pragma unroll
            for (int off = 1; off <= 8; off <<= 1) {
                unsigned long long o = __shfl_xor_sync(0xffffffffu, pk, off);
                if (o < pk) pk = o;
            }
            if (tx == 0) atomicMin(&g_best[rows[i]], pk);
        }
    }
}

// ---------------------------------------------------------------------------
// Fixup gather for flagged rows
// ---------------------------------------------------------------------------
__global__ void vq_fix_kernel(const float* __restrict__ emb,
                              float* __restrict__ out) {
    int cnt = g_flagcnt;
    for (int j = blockIdx.x; j < cnt; j += gridDim.x) {
        int row = g_flagrows[j];
        unsigned idx = (unsigned)(g_best[row] & 0xffffffffu);
        const float4* src = reinterpret_cast<const float4*>(emb + (size_t)idx * DIMS);
        float4*       dst = reinterpret_cast<float4*>(out + (size_t)row * DIMS);
        for (int v = threadIdx.x; v < DIMS / 4; v += blockDim.x)
            dst[v] = src[v];
    }
}

// ---------------------------------------------------------------------------
// Launch
// ---------------------------------------------------------------------------
extern "C" void kernel_launch(void* const* d_in, const int* in_sizes, int n_in,
                              void* d_out, int out_size) {
    const float* z   = (const float*)d_in[0];   // [32,2048,512] fp32
    const float* emb = (const float*)d_in[1];   // [1024,512] fp32
    float* out = (float*)d_out;

    enorm_kernel<<<(CODES * 32 + 255) / 256, 256>>>(emb);   // also resets flagcnt
    znorm_kernel<<<(NROWS * 32 + 255) / 256, 256>>>(z);
    vq_mma_kernel<<<NROWS / MT, 256>>>(z, emb, out);
    vq_exact_kernel<<<512, 256>>>(z, emb);
    vq_fix_kernel<<<128, 128>>>(emb, out);
}

// round 7
// speedup vs baseline: 2.1095x; 1.7649x over previous
#include <cuda_runtime.h>
#include <cstdint>

// Problem constants
#define NROWS 65536   // 32 * 2048
#define DIMS  512
#define CODES 1024

#define MT  128       // rows per CTA (TC kernel)
#define NT2 128       // codes per tile
#define KC  16        // K floats per staged chunk
#define NCH (DIMS / KC)      // 32 chunks
#define NTL (CODES / NT2)    // 8 tiles

#define MARGIN 2.5e-4f       // 12.5 sigma of the 1xTF32 score error; > 3 grid-ulps

// Scratch (device globals — allocation is forbidden)
__device__ float g_enorm[CODES];
__device__ float g_znorm[NROWS];
__device__ int   g_flagcnt;
__device__ int   g_flagrows[NROWS];
__device__ unsigned long long g_best[NROWS];

// ---------------------------------------------------------------------------
// Helpers
// ---------------------------------------------------------------------------
__device__ __forceinline__ float tf32r(float x) {
    uint32_t r;
    asm("cvt.rna.tf32.f32 %0, %1;" : "=r"(r) : "f"(x));
    return __uint_as_float(r);
}

__device__ __forceinline__ void mma_tf32(float* c,
                                         uint32_t a0, uint32_t a1, uint32_t a2, uint32_t a3,
                                         uint32_t b0, uint32_t b1) {
    asm volatile(
        "mma.sync.aligned.m16n8k8.row.col.f32.tf32.tf32.f32 "
        "{%0,%1,%2,%3}, {%4,%5,%6,%7}, {%8,%9}, {%0,%1,%2,%3};"
        : "+f"(c[0]), "+f"(c[1]), "+f"(c[2]), "+f"(c[3])
        : "r"(a0), "r"(a1), "r"(a2), "r"(a3), "r"(b0), "r"(b1));
}

// swizzled smem index for a [128][16] float tile
__device__ __forceinline__ int lds_idx(int r, int k) {
    return (r << 4) + ((((k >> 2) ^ ((r >> 1) & 3)) & 3) << 2) + (k & 3);
}

// ---------------------------------------------------------------------------
// Norm kernels (fp64 accumulate -> fp32), one warp per row
// ---------------------------------------------------------------------------
__global__ void enorm_kernel(const float* __restrict__ emb) {
    if (blockIdx.x == 0 && threadIdx.x == 0) g_flagcnt = 0;  // reset per replay
    int warp = (blockIdx.x * blockDim.x + threadIdx.x) >> 5;
    int lane = threadIdx.x & 31;
    if (warp >= CODES) return;
    const float4* row = reinterpret_cast<const float4*>(emb + (size_t)warp * DIMS);
    double s = 0.0;
#pragma unroll
    for (int i = 0; i < 4; i++) {
        float4 v = row[lane + i * 32];
        s += (double)v.x * v.x + (double)v.y * v.y
           + (double)v.z * v.z + (double)v.w * v.w;
    }
#pragma unroll
    for (int off = 16; off > 0; off >>= 1)
        s += __shfl_xor_sync(0xffffffffu, s, off);
    if (lane == 0) g_enorm[warp] = (float)s;
}

__global__ void znorm_kernel(const float* __restrict__ z) {
    int warp = (blockIdx.x * blockDim.x + threadIdx.x) >> 5;
    int lane = threadIdx.x & 31;
    if (warp >= NROWS) return;
    const float4* row = reinterpret_cast<const float4*>(z + (size_t)warp * DIMS);
    double s = 0.0;
#pragma unroll
    for (int i = 0; i < 4; i++) {
        float4 v = row[lane + i * 32];
        s += (double)v.x * v.x + (double)v.y * v.y
           + (double)v.z * v.z + (double)v.w * v.w;
    }
#pragma unroll
    for (int off = 16; off > 0; off >>= 1)
        s += __shfl_xor_sync(0xffffffffu, s, off);
    if (lane == 0) g_znorm[warp] = (float)s;
}

// ---------------------------------------------------------------------------
// TC kernel: single-pass TF32 mma.sync GEMM + top-2 argmin + flag + gather
// ---------------------------------------------------------------------------
__global__ __launch_bounds__(256, 2)
void vq_mma_kernel(const float* __restrict__ z,
                   const float* __restrict__ emb,
                   float* __restrict__ out) {
    __shared__ __align__(16) float sAh[128 * KC];
    __shared__ __align__(16) float sBh[128 * KC];
    __shared__ float sbest[128 * 4];
    __shared__ float sb2  [128 * 4];
    __shared__ int   sidn [128 * 4];
    __shared__ int   srow [128];

    const int t    = threadIdx.x;
    const int lane = t & 31;
    const int wid  = t >> 5;
    const int row0 = blockIdx.x * MT;
    const int wm = (wid & 1) * 64;
    const int wn = (wid >> 1) * 32;
    const int lr4 = lane >> 2;
    const int lc  = lane & 3;

    float zn[8];
#pragma unroll
    for (int mi = 0; mi < 4; mi++)
#pragma unroll
        for (int h = 0; h < 2; h++)
            zn[mi * 2 + h] = g_znorm[row0 + wm + mi * 16 + lr4 + h * 8];

    float best[8], b2[8];
    int   bidx[8];
#pragma unroll
    for (int i = 0; i < 8; i++) { best[i] = 3.4e38f; b2[i] = 3.4e38f; bidx[i] = 0; }

    for (int nt = 0; nt < NTL; nt++) {
        const int n0 = nt * NT2;

        float acc[4][4][4];
#pragma unroll
        for (int mi = 0; mi < 4; mi++)
#pragma unroll
            for (int nj = 0; nj < 4; nj++)
#pragma unroll
                for (int q = 0; q < 4; q++) acc[mi][nj][q] = 0.f;

        float4 pa[2], pb[2];
#pragma unroll
        for (int i = 0; i < 2; i++) {
            int v = t + 256 * i;
            int r = v >> 2, q = v & 3;
            pa[i] = *reinterpret_cast<const float4*>(z   + (size_t)(row0 + r) * DIMS + q * 4);
            pb[i] = *reinterpret_cast<const float4*>(emb + (size_t)(n0  + r) * DIMS + q * 4);
        }

        for (int c = 0; c < NCH; c++) {
            __syncthreads();
#pragma unroll
            for (int i = 0; i < 2; i++) {
                int v = t + 256 * i;
                int r = v >> 2, q = v & 3;
                int off = (r << 4) + (((q ^ ((r >> 1) & 3)) & 3) << 2);

                float4 x = pa[i];
                float4 hi;
                hi.x = tf32r(x.x); hi.y = tf32r(x.y);
                hi.z = tf32r(x.z); hi.w = tf32r(x.w);
                *reinterpret_cast<float4*>(&sAh[off]) = hi;

                x = pb[i];
                hi.x = tf32r(x.x); hi.y = tf32r(x.y);
                hi.z = tf32r(x.z); hi.w = tf32r(x.w);
                *reinterpret_cast<float4*>(&sBh[off]) = hi;
            }
            __syncthreads();

            if (c + 1 < NCH) {
                const int k0n = (c + 1) * KC;
#pragma unroll
                for (int i = 0; i < 2; i++) {
                    int v = t + 256 * i;
                    int r = v >> 2, q = v & 3;
                    pa[i] = *reinterpret_cast<const float4*>(
                        z   + (size_t)(row0 + r) * DIMS + k0n + q * 4);
                    pb[i] = *reinterpret_cast<const float4*>(
                        emb + (size_t)(n0  + r) * DIMS + k0n + q * 4);
                }
            }

#pragma unroll
            for (int ks = 0; ks < 2; ks++) {
                uint32_t Bh[4][2];
#pragma unroll
                for (int nj = 0; nj < 4; nj++) {
                    int n = wn + nj * 8 + lr4;
                    int k = ks * 8 + lc;
                    Bh[nj][0] = __float_as_uint(sBh[lds_idx(n, k)]);
                    Bh[nj][1] = __float_as_uint(sBh[lds_idx(n, k + 4)]);
                }
#pragma unroll
                for (int mi = 0; mi < 4; mi++) {
                    int r = wm + mi * 16 + lr4;
                    int k = ks * 8 + lc;
                    uint32_t Ah0 = __float_as_uint(sAh[lds_idx(r,     k)]);
                    uint32_t Ah1 = __float_as_uint(sAh[lds_idx(r + 8, k)]);
                    uint32_t Ah2 = __float_as_uint(sAh[lds_idx(r,     k + 4)]);
                    uint32_t Ah3 = __float_as_uint(sAh[lds_idx(r + 8, k + 4)]);
#pragma unroll
                    for (int nj = 0; nj < 4; nj++)
                        mma_tf32(acc[mi][nj], Ah0, Ah1, Ah2, Ah3, Bh[nj][0], Bh[nj][1]);
                }
            }
        }

        // ---- epilogue: ref-rounding score + running top-2 ----
#pragma unroll
        for (int mi = 0; mi < 4; mi++) {
#pragma unroll
            for (int nj = 0; nj < 4; nj++) {
                int cbase = n0 + wn + nj * 8 + 2 * lc;
                float en0 = __ldg(&g_enorm[cbase]);
                float en1 = __ldg(&g_enorm[cbase + 1]);
                const float* cc = acc[mi][nj];
#pragma unroll
                for (int h = 0; h < 2; h++) {
                    int s0i = mi * 2 + h;
                    float s0 = __fsub_rn(__fadd_rn(zn[s0i], en0), __fmul_rn(2.0f, cc[h * 2]));
                    float s1 = __fsub_rn(__fadd_rn(zn[s0i], en1), __fmul_rn(2.0f, cc[h * 2 + 1]));
                    if (s0 < best[s0i]) { b2[s0i] = best[s0i]; best[s0i] = s0; bidx[s0i] = cbase; }
                    else if (s0 < b2[s0i]) b2[s0i] = s0;
                    if (s1 < best[s0i]) { b2[s0i] = best[s0i]; best[s0i] = s1; bidx[s0i] = cbase + 1; }
                    else if (s1 < b2[s0i]) b2[s0i] = s1;
                }
            }
        }
    }

    // ---- cross-lane top-2 merge (lanes sharing a row: lc group) ----
#pragma unroll
    for (int s = 0; s < 8; s++) {
#pragma unroll
        for (int off = 1; off <= 2; off <<= 1) {
            float vb  = __shfl_xor_sync(0xffffffffu, best[s], off);
            float vb2 = __shfl_xor_sync(0xffffffffu, b2[s],   off);
            int   vi  = __shfl_xor_sync(0xffffffffu, bidx[s], off);
            if (vb < best[s]) { b2[s] = fminf(best[s], vb2); best[s] = vb; bidx[s] = vi; }
            else if (vb > best[s]) { b2[s] = fminf(b2[s], vb); }
            else { bidx[s] = min(bidx[s], vi); b2[s] = vb; }
        }
    }
    __syncthreads();
    if (lc == 0) {
#pragma unroll
        for (int mi = 0; mi < 4; mi++)
#pragma unroll
            for (int h = 0; h < 2; h++) {
                int r = wm + mi * 16 + lr4 + h * 8;
                sbest[r * 4 + (wid >> 1)] = best[mi * 2 + h];
                sb2  [r * 4 + (wid >> 1)] = b2  [mi * 2 + h];
                sidn [r * 4 + (wid >> 1)] = bidx[mi * 2 + h];
            }
    }
    __syncthreads();

    if (t < 128) {
        float b  = sbest[t * 4];
        float bb = sb2  [t * 4];
        int   bi = sidn [t * 4];
#pragma unroll
        for (int x = 1; x < 4; x++) {
            float v  = sbest[t * 4 + x];
            float v2 = sb2  [t * 4 + x];
            int   vi = sidn [t * 4 + x];
            if (v < b) { bb = fminf(b, v2); b = v; bi = vi; }
            else if (v > b) { bb = fminf(bb, v); }
            else { bi = min(bi, vi); bb = v; }
        }
        srow[t] = bi;
        if (__fsub_rn(bb, b) < MARGIN) {   // ambiguous -> exact recompute
            int row = row0 + t;
            g_best[row] = ~0ULL;
            int p = atomicAdd(&g_flagcnt, 1);
            g_flagrows[p] = row;
        }
    }
    __syncthreads();

    // ---- gather: out[row] = emb[idx] (flagged rows fixed later) ----
    float4*       out4 = reinterpret_cast<float4*>(out + (size_t)row0 * DIMS);
    const float4* emb4 = reinterpret_cast<const float4*>(emb);
    for (int v = t; v < 128 * (DIMS / 4); v += 256) {
        int r  = v >> 7;
        int c4 = v & 127;
        out4[(size_t)r * 128 + c4] = emb4[(size_t)srow[r] * 128 + c4];
    }
}

// ---------------------------------------------------------------------------
// Exact fallback: R2-identical arithmetic for flagged rows.
//   One block = 64 flagged rows x 128-code group; dot = ascending-k fmaf
//   chain in 16-chunks (bit-identical to the R2 kernel that scored 0.0).
//   Per-row merge across code groups via packed atomicMin (tie -> lowest idx).
// ---------------------------------------------------------------------------
__global__ __launch_bounds__(256)
void vq_exact_kernel(const float* __restrict__ z,
                     const float* __restrict__ emb) {
    __shared__ float Zs[16 * 64];
    __shared__ float Es[16 * 128];
    __shared__ int   rlist[64];

    const int t  = threadIdx.x;
    const int tx = t & 15;    // 8 codes each
    const int ty = t >> 4;    // 4 rows each

    int cnt = g_flagcnt;
    if (cnt <= 0) return;
    int tb = (cnt + 63) >> 6;
    int total = tb * 8;

    for (int task = blockIdx.x; task < total; task += gridDim.x) {
        int rb = task >> 3;
        int cg = task & 7;
        int c0 = cg * 128;

        __syncthreads();
        if (t < 64) {
            int j = rb * 64 + t;
            rlist[t] = g_flagrows[j < cnt ? j : cnt - 1];
        }
        __syncthreads();

        float zn[4];
        int rows[4];
#pragma unroll
        for (int i = 0; i < 4; i++) {
            rows[i] = rlist[ty * 4 + i];
            zn[i] = g_znorm[rows[i]];
        }
        float en[8];
#pragma unroll
        for (int j = 0; j < 8; j++) en[j] = g_enorm[c0 + tx * 8 + j];

        float acc[4][8];
#pragma unroll
        for (int i = 0; i < 4; i++)
#pragma unroll
            for (int j = 0; j < 8; j++) acc[i][j] = 0.f;

        for (int c = 0; c < NCH; c++) {
            const int k0 = c * KC;
            __syncthreads();
            {   // stage Z: 64 rows x 16 K, [k][row]
                int r = t >> 2, q = t & 3;
                float4 x = *reinterpret_cast<const float4*>(
                    z + (size_t)rlist[r] * DIMS + k0 + q * 4);
                Zs[(q * 4 + 0) * 64 + r] = x.x;
                Zs[(q * 4 + 1) * 64 + r] = x.y;
                Zs[(q * 4 + 2) * 64 + r] = x.z;
                Zs[(q * 4 + 3) * 64 + r] = x.w;
            }
#pragma unroll
            for (int i = 0; i < 2; i++) {   // stage E: 128 codes x 16 K
                int v = t + 256 * i;
                int r = v >> 2, q = v & 3;
                float4 x = *reinterpret_cast<const float4*>(
                    emb + (size_t)(c0 + r) * DIMS + k0 + q * 4);
                Es[(q * 4 + 0) * 128 + r] = x.x;
                Es[(q * 4 + 1) * 128 + r] = x.y;
                Es[(q * 4 + 2) * 128 + r] = x.z;
                Es[(q * 4 + 3) * 128 + r] = x.w;
            }
            __syncthreads();

#pragma unroll
            for (int k = 0; k < 16; k++) {
                float zf[4], ef[8];
#pragma unroll
                for (int i = 0; i < 4; i++) zf[i] = Zs[k * 64 + ty * 4 + i];
#pragma unroll
                for (int j = 0; j < 8; j++) ef[j] = Es[k * 128 + tx * 8 + j];
#pragma unroll
                for (int i = 0; i < 4; i++)
#pragma unroll
                    for (int j = 0; j < 8; j++)
                        acc[i][j] = fmaf(zf[i], ef[j], acc[i][j]);
            }
        }

        // score + per-thread argmin (codes ascending -> strict < keeps lowest)
#pragma unroll
        for (int i = 0; i < 4; i++) {
            float bb = 3.4e38f;
            int   bi = 0;
#pragma unroll
            for (int j = 0; j < 8; j++) {
                float s = __fsub_rn(__fadd_rn(zn[i], en[j]),
                                    __fmul_rn(2.0f, acc[i][j]));
                if (s < bb) { bb = s; bi = c0 + tx * 8 + j; }
            }
            unsigned long long pk =
                ((unsigned long long)__float_as_uint(bb) << 32) | (unsigned)bi;
#pragma unroll
            for (int off = 1; off <= 8; off <<= 1) {
                unsigned long long o = __shfl_xor_sync(0xffffffffu, pk, off);
                if (o < pk) pk = o;
            }
            if (tx == 0) atomicMin(&g_best[rows[i]], pk);
        }
    }
}

// ---------------------------------------------------------------------------
// Fixup gather for flagged rows
// ---------------------------------------------------------------------------
__global__ void vq_fix_kernel(const float* __restrict__ emb,
                              float* __restrict__ out) {
    int cnt = g_flagcnt;
    for (int j = blockIdx.x; j < cnt; j += gridDim.x) {
        int row = g_flagrows[j];
        unsigned idx = (unsigned)(g_best[row] & 0xffffffffu);
        const float4* src = reinterpret_cast<const float4*>(emb + (size_t)idx * DIMS);
        float4*       dst = reinterpret_cast<float4*>(out + (size_t)row * DIMS);
        for (int v = threadIdx.x; v < DIMS / 4; v += blockDim.x)
            dst[v] = src[v];
    }
}

// ---------------------------------------------------------------------------
// Launch
// ---------------------------------------------------------------------------
extern "C" void kernel_launch(void* const* d_in, const int* in_sizes, int n_in,
                              void* d_out, int out_size) {
    const float* z   = (const float*)d_in[0];   // [32,2048,512] fp32
    const float* emb = (const float*)d_in[1];   // [1024,512] fp32
    float* out = (float*)d_out;

    enorm_kernel<<<(CODES * 32 + 255) / 256, 256>>>(emb);   // also resets flagcnt
    znorm_kernel<<<(NROWS * 32 + 255) / 256, 256>>>(z);
    vq_mma_kernel<<<NROWS / MT, 256>>>(z, emb, out);
    vq_exact_kernel<<<512, 256>>>(z, emb);
    vq_fix_kernel<<<128, 128>>>(emb, out);
}